// round 1
// baseline (speedup 1.0000x reference)
#include <cuda_runtime.h>
#include <math.h>

#define SEQ   2048
#define DMODEL 2048
#define NHEAD 32
#define NKV   8
#define HDIM  64
#define NEXP  8
#define FDIM  7168
#define NTOK  2048
#define NSLOT 4096
#define EPSF  1e-5f

// ----------------------------- scratch (device globals; no runtime alloc) ---
__device__ float g_hnorm[NTOK * DMODEL];
__device__ float g_q[NTOK * NHEAD * HDIM];
__device__ float g_k[NTOK * NKV * HDIM];
__device__ float g_v[NTOK * NKV * HDIM];
__device__ float g_attn[NTOK * DMODEL];
__device__ float g_h2[NTOK * DMODEL];
__device__ float g_tnorm[NTOK * DMODEL];
__device__ int   g_topi[NTOK * 2];
__device__ float g_topw[NTOK * 2];
__device__ int   g_slot_token[NSLOT];
__device__ int   g_slot_of[NTOK * 2];
__device__ int   g_off[NEXP + 1];
__device__ float g_act[(size_t)NSLOT * FDIM];    // silu(gate)*up per slot
__device__ float g_down[(size_t)NSLOT * DMODEL]; // expert down output per slot

// ----------------------------- RMSNorm --------------------------------------
__global__ __launch_bounds__(256) void rmsnorm_kernel(
    const float* __restrict__ x, const float* __restrict__ w, float* __restrict__ y)
{
    int row = blockIdx.x;
    const float* xr = x + (size_t)row * DMODEL;
    __shared__ float red[256];
    float ss = 0.f;
    const float4* x4 = (const float4*)xr;
    for (int i = threadIdx.x; i < DMODEL / 4; i += 256) {
        float4 v = x4[i];
        ss += v.x * v.x + v.y * v.y + v.z * v.z + v.w * v.w;
    }
    red[threadIdx.x] = ss;
    __syncthreads();
    for (int s = 128; s > 0; s >>= 1) {
        if (threadIdx.x < s) red[threadIdx.x] += red[threadIdx.x + s];
        __syncthreads();
    }
    float inv = rsqrtf(red[0] / (float)DMODEL + EPSF);
    for (int i = threadIdx.x; i < DMODEL; i += 256)
        y[(size_t)row * DMODEL + i] = xr[i] * inv * w[i];
}

// ----------------------------- generic SGEMM (dims multiples of 64) ---------
// C[M,N] = A[M,K] @ B[K,N]  (+ res), all row-major fp32.
__global__ __launch_bounds__(256) void sgemm_kernel(
    const float* __restrict__ A, const float* __restrict__ B,
    float* __restrict__ C, const float* __restrict__ res,
    int M, int N, int K)
{
    __shared__ float As[16][64];   // transposed: As[k][m]
    __shared__ float Bs[16][64];   // Bs[k][n]
    int tid = threadIdx.x;
    int m0 = blockIdx.y * 64, n0 = blockIdx.x * 64;
    int row = (tid >> 4) * 4, col = (tid & 15) * 4;
    int lm = tid >> 2, lk = (tid & 3) * 4;
    int bk = tid >> 4, bn = (tid & 15) * 4;
    const float* aptr = A + (size_t)(m0 + lm) * K + lk;
    const float* bptr = B + (size_t)bk * N + n0 + bn;
    float acc[4][4] = {};
    for (int k0 = 0; k0 < K; k0 += 16) {
        float4 av = *(const float4*)(aptr + k0);
        As[lk + 0][lm] = av.x; As[lk + 1][lm] = av.y;
        As[lk + 2][lm] = av.z; As[lk + 3][lm] = av.w;
        *(float4*)&Bs[bk][bn] = *(const float4*)(bptr + (size_t)k0 * N);
        __syncthreads();
#pragma unroll
        for (int kk = 0; kk < 16; kk++) {
            float4 a = *(float4*)&As[kk][row];
            float4 b = *(float4*)&Bs[kk][col];
            float ar[4] = {a.x, a.y, a.z, a.w};
            float br[4] = {b.x, b.y, b.z, b.w};
#pragma unroll
            for (int i = 0; i < 4; i++)
#pragma unroll
                for (int j = 0; j < 4; j++) acc[i][j] += ar[i] * br[j];
        }
        __syncthreads();
    }
#pragma unroll
    for (int i = 0; i < 4; i++) {
        size_t off = (size_t)(m0 + row + i) * N + n0 + col;
        float4 c = make_float4(acc[i][0], acc[i][1], acc[i][2], acc[i][3]);
        if (res) {
            float4 r = *(const float4*)(res + off);
            c.x += r.x; c.y += r.y; c.z += r.z; c.w += r.w;
        }
        *(float4*)(C + off) = c;
    }
}

// ----------------------------- RoPE (in place) -------------------------------
__global__ void rope_kernel(float* __restrict__ x, const int* __restrict__ pos, int nheads)
{
    int s = blockIdx.x, h = blockIdx.y, i = threadIdx.x; // 32 threads
    float p = (float)pos[s];
    // inv = ROPE_BASE^{-(2i/HD)} = exp(-(2i/64)*ln(1e6))
    float inv = expf(-((float)(2 * i) / 64.f) * 13.815510557964274f);
    float ang = p * inv;
    float sn, cs;
    sincosf(ang, &sn, &cs);
    float* xp = x + ((size_t)s * nheads + h) * HDIM;
    float x1 = xp[i], x2 = xp[i + 32];
    xp[i]      = x1 * cs - x2 * sn;
    xp[i + 32] = x2 * cs + x1 * sn;
}

// ----------------------------- flash attention (causal, GQA) ----------------
// grid: (SEQ/64, NKV); 256 threads = 64 q-positions x 4 q-heads sharing K/V head.
__global__ __launch_bounds__(256) void flash_kernel(float* __restrict__ out)
{
    int bq = blockIdx.x, kvh = blockIdx.y;
    int tid = threadIdx.x;
    int ql = tid & 63, sub = tid >> 6;
    int qpos = bq * 64 + ql;
    int qh = kvh * 4 + sub;
    __shared__ float Ks[32][64];
    __shared__ float Vs[32][64];
    float qreg[64], o[64];
    const float* qp = g_q + ((size_t)qpos * NHEAD + qh) * HDIM;
#pragma unroll
    for (int d = 0; d < 64; d++) { qreg[d] = qp[d] * 0.125f; o[d] = 0.f; }
    float m = -INFINITY, l = 0.f;
    int kend = bq * 64 + 64;
    for (int kt = 0; kt < kend; kt += 32) {
        for (int i = tid; i < 32 * 16; i += 256) {   // 512 float4 loads per buffer
            int j = i >> 4, d4 = (i & 15) * 4;
            *(float4*)&Ks[j][d4] = *(const float4*)(g_k + ((size_t)(kt + j) * NKV + kvh) * HDIM + d4);
            *(float4*)&Vs[j][d4] = *(const float4*)(g_v + ((size_t)(kt + j) * NKV + kvh) * HDIM + d4);
        }
        __syncthreads();
        int jmax = qpos - kt + 1;
        if (jmax > 32) jmax = 32;
        for (int j = 0; j < jmax; j++) {
            float s = 0.f;
#pragma unroll
            for (int d = 0; d < 64; d++) s += qreg[d] * Ks[j][d];
            float mn = fmaxf(m, s);
            float corr = expf(m - mn);
            float p = expf(s - mn);
            l = l * corr + p;
#pragma unroll
            for (int d = 0; d < 64; d++) o[d] = o[d] * corr + p * Vs[j][d];
            m = mn;
        }
        __syncthreads();
    }
    float invl = 1.f / l;
    float* op = out + ((size_t)qpos * NHEAD + qh) * HDIM;
#pragma unroll
    for (int d = 0; d < 64; d++) op[d] = o[d] * invl;
}

// ----------------------------- router: logits + top-2 + renorm --------------
__global__ __launch_bounds__(128) void router_kernel(
    const float* __restrict__ T, const float* __restrict__ Wr)
{
    int t = blockIdx.x;
    __shared__ float sred[128 * 8];
    float acc[8] = {};
    const float* tr = T + (size_t)t * DMODEL;
    for (int d = threadIdx.x; d < DMODEL; d += 128) {
        float x = tr[d];
        const float* wr = Wr + (size_t)d * NEXP;
#pragma unroll
        for (int e = 0; e < 8; e++) acc[e] += x * wr[e];
    }
#pragma unroll
    for (int e = 0; e < 8; e++) sred[threadIdx.x * 8 + e] = acc[e];
    __syncthreads();
    for (int s = 64; s > 0; s >>= 1) {
        if (threadIdx.x < s) {
#pragma unroll
            for (int e = 0; e < 8; e++)
                sred[threadIdx.x * 8 + e] += sred[(threadIdx.x + s) * 8 + e];
        }
        __syncthreads();
    }
    if (threadIdx.x == 0) {
        float best = -1e30f, second = -1e30f;
        int bi = 0, si = 0;
#pragma unroll
        for (int e = 0; e < 8; e++) {
            float v = sred[e];
            if (v > best)      { second = best; si = bi; best = v; bi = e; }
            else if (v > second) { second = v; si = e; }
        }
        // renormalized top-2 softmax weights: softmax norm cancels
        float p0 = 1.f / (1.f + expf(second - best));
        g_topi[2 * t] = bi;  g_topi[2 * t + 1] = si;
        g_topw[2 * t] = p0;  g_topw[2 * t + 1] = 1.f - p0;
    }
}

// ----------------------------- expert assignment (1 block) ------------------
__global__ __launch_bounds__(256) void assign_kernel()
{
    __shared__ int cnt[NEXP], base[NEXP + 1], cur[NEXP];
    if (threadIdx.x < NEXP) cnt[threadIdx.x] = 0;
    __syncthreads();
    for (int t = threadIdx.x; t < NTOK; t += 256) {
        atomicAdd(&cnt[g_topi[2 * t]], 1);
        atomicAdd(&cnt[g_topi[2 * t + 1]], 1);
    }
    __syncthreads();
    if (threadIdx.x == 0) {
        int s = 0;
        for (int e = 0; e < NEXP; e++) { base[e] = s; s += cnt[e]; }
        base[NEXP] = s;
    }
    __syncthreads();
    if (threadIdx.x < NEXP) cur[threadIdx.x] = base[threadIdx.x];
    if (threadIdx.x < NEXP + 1) g_off[threadIdx.x] = base[threadIdx.x];
    __syncthreads();
    for (int t = threadIdx.x; t < NTOK; t += 256) {
#pragma unroll
        for (int k = 0; k < 2; k++) {
            int e = g_topi[2 * t + k];
            int slot = atomicAdd(&cur[e], 1);
            g_slot_token[slot] = t;
            g_slot_of[2 * t + k] = slot;
        }
    }
}

// ----------------------------- grouped gate+up GEMM with SiLU ---------------
// act[slot, f] = silu(T@W1[e]) * (T@W3[e]) over this expert's gathered tokens.
__global__ __launch_bounds__(256) void moe_gateup_kernel(
    const float* __restrict__ T, const float* __restrict__ W1, const float* __restrict__ W3)
{
    int e = blockIdx.z;
    int rbeg = g_off[e], rend = g_off[e + 1];
    int rows = rend - rbeg;
    int m0 = blockIdx.y * 64;
    if (m0 >= rows) return;
    int n0 = blockIdx.x * 64;
    const float* B1 = W1 + (size_t)e * DMODEL * FDIM;
    const float* B2 = W3 + (size_t)e * DMODEL * FDIM;
    __shared__ float As[16][64];
    __shared__ float B1s[16][64];
    __shared__ float B2s[16][64];
    int tid = threadIdx.x;
    int row = (tid >> 4) * 4, col = (tid & 15) * 4;
    int lm = tid >> 2, lk = (tid & 3) * 4;
    int bk = tid >> 4, bn = (tid & 15) * 4;
    const float* arow = nullptr;
    if (m0 + lm < rows)
        arow = T + (size_t)g_slot_token[rbeg + m0 + lm] * DMODEL + lk;
    const float* b1ptr = B1 + (size_t)bk * FDIM + n0 + bn;
    const float* b2ptr = B2 + (size_t)bk * FDIM + n0 + bn;
    float accg[4][4] = {}, accu[4][4] = {};
    for (int k0 = 0; k0 < DMODEL; k0 += 16) {
        float4 av = arow ? *(const float4*)(arow + k0) : make_float4(0.f, 0.f, 0.f, 0.f);
        As[lk + 0][lm] = av.x; As[lk + 1][lm] = av.y;
        As[lk + 2][lm] = av.z; As[lk + 3][lm] = av.w;
        *(float4*)&B1s[bk][bn] = *(const float4*)(b1ptr + (size_t)k0 * FDIM);
        *(float4*)&B2s[bk][bn] = *(const float4*)(b2ptr + (size_t)k0 * FDIM);
        __syncthreads();
#pragma unroll
        for (int kk = 0; kk < 16; kk++) {
            float4 a  = *(float4*)&As[kk][row];
            float4 b1 = *(float4*)&B1s[kk][col];
            float4 b2 = *(float4*)&B2s[kk][col];
            float ar[4] = {a.x, a.y, a.z, a.w};
            float g1[4] = {b1.x, b1.y, b1.z, b1.w};
            float g2[4] = {b2.x, b2.y, b2.z, b2.w};
#pragma unroll
            for (int i = 0; i < 4; i++)
#pragma unroll
                for (int j = 0; j < 4; j++) {
                    accg[i][j] += ar[i] * g1[j];
                    accu[i][j] += ar[i] * g2[j];
                }
        }
        __syncthreads();
    }
#pragma unroll
    for (int i = 0; i < 4; i++) {
        int mloc = m0 + row + i;
        if (mloc < rows) {
            size_t slot = (size_t)(rbeg + mloc);
#pragma unroll
            for (int j = 0; j < 4; j++) {
                float g = accg[i][j], u = accu[i][j];
                float sg = g / (1.f + expf(-g));
                g_act[slot * FDIM + n0 + col + j] = sg * u;
            }
        }
    }
}

// ----------------------------- grouped down GEMM -----------------------------
__global__ __launch_bounds__(256) void moe_down_kernel(const float* __restrict__ W2)
{
    int e = blockIdx.z;
    int rbeg = g_off[e], rend = g_off[e + 1];
    int rows = rend - rbeg;
    int m0 = blockIdx.y * 64;
    if (m0 >= rows) return;
    int n0 = blockIdx.x * 64;
    const float* B = W2 + (size_t)e * FDIM * DMODEL;
    __shared__ float As[16][64];
    __shared__ float Bs[16][64];
    int tid = threadIdx.x;
    int row = (tid >> 4) * 4, col = (tid & 15) * 4;
    int lm = tid >> 2, lk = (tid & 3) * 4;
    int bk = tid >> 4, bn = (tid & 15) * 4;
    const float* arow = nullptr;
    if (m0 + lm < rows)
        arow = g_act + (size_t)(rbeg + m0 + lm) * FDIM + lk;
    const float* bptr = B + (size_t)bk * DMODEL + n0 + bn;
    float acc[4][4] = {};
    for (int k0 = 0; k0 < FDIM; k0 += 16) {
        float4 av = arow ? *(const float4*)(arow + k0) : make_float4(0.f, 0.f, 0.f, 0.f);
        As[lk + 0][lm] = av.x; As[lk + 1][lm] = av.y;
        As[lk + 2][lm] = av.z; As[lk + 3][lm] = av.w;
        *(float4*)&Bs[bk][bn] = *(const float4*)(bptr + (size_t)k0 * DMODEL);
        __syncthreads();
#pragma unroll
        for (int kk = 0; kk < 16; kk++) {
            float4 a = *(float4*)&As[kk][row];
            float4 b = *(float4*)&Bs[kk][col];
            float ar[4] = {a.x, a.y, a.z, a.w};
            float br[4] = {b.x, b.y, b.z, b.w};
#pragma unroll
            for (int i = 0; i < 4; i++)
#pragma unroll
                for (int j = 0; j < 4; j++) acc[i][j] += ar[i] * br[j];
        }
        __syncthreads();
    }
#pragma unroll
    for (int i = 0; i < 4; i++) {
        int mloc = m0 + row + i;
        if (mloc < rows) {
            size_t slot = (size_t)(rbeg + mloc);
            float4 c = make_float4(acc[i][0], acc[i][1], acc[i][2], acc[i][3]);
            *(float4*)(g_down + slot * DMODEL + n0 + col) = c;
        }
    }
}

// ----------------------------- final combine ---------------------------------
__global__ __launch_bounds__(256) void combine_kernel(
    const float* __restrict__ h2, float* __restrict__ out)
{
    int t = blockIdx.x;
    int s0 = g_slot_of[2 * t], s1 = g_slot_of[2 * t + 1];
    float w0 = g_topw[2 * t], w1 = g_topw[2 * t + 1];
    const float* d0 = g_down + (size_t)s0 * DMODEL;
    const float* d1 = g_down + (size_t)s1 * DMODEL;
    const float* hr = h2 + (size_t)t * DMODEL;
    float* orow = out + (size_t)t * DMODEL;
    for (int d = threadIdx.x; d < DMODEL; d += 256)
        orow[d] = hr[d] + w0 * d0[d] + w1 * d1[d];
}

// ----------------------------- launch ---------------------------------------
extern "C" void kernel_launch(void* const* d_in, const int* in_sizes, int n_in,
                              void* d_out, int out_size)
{
    const float* hs   = (const float*)d_in[0];
    const int*   pos  = (const int*)d_in[1];
    const float* ln1w = (const float*)d_in[2];
    const float* Wq   = (const float*)d_in[3];
    const float* Wk   = (const float*)d_in[4];
    const float* Wv   = (const float*)d_in[5];
    const float* Wo   = (const float*)d_in[6];
    const float* ln2w = (const float*)d_in[7];
    const float* Wr   = (const float*)d_in[8];
    const float* W1   = (const float*)d_in[9];
    const float* W3   = (const float*)d_in[10];
    const float* W2   = (const float*)d_in[11];
    float* out = (float*)d_out;

    float *hnorm, *q, *k, *v, *attn, *h2, *tnorm;
    cudaGetSymbolAddress((void**)&hnorm, g_hnorm);
    cudaGetSymbolAddress((void**)&q, g_q);
    cudaGetSymbolAddress((void**)&k, g_k);
    cudaGetSymbolAddress((void**)&v, g_v);
    cudaGetSymbolAddress((void**)&attn, g_attn);
    cudaGetSymbolAddress((void**)&h2, g_h2);
    cudaGetSymbolAddress((void**)&tnorm, g_tnorm);

    // 1. RMSNorm 1
    rmsnorm_kernel<<<NTOK, 256>>>(hs, ln1w, hnorm);
    // 2. QKV projections
    sgemm_kernel<<<dim3(DMODEL / 64, NTOK / 64), 256>>>(hnorm, Wq, q, nullptr, NTOK, DMODEL, DMODEL);
    sgemm_kernel<<<dim3(512 / 64, NTOK / 64), 256>>>(hnorm, Wk, k, nullptr, NTOK, 512, DMODEL);
    sgemm_kernel<<<dim3(512 / 64, NTOK / 64), 256>>>(hnorm, Wv, v, nullptr, NTOK, 512, DMODEL);
    // 3. RoPE on q and k
    rope_kernel<<<dim3(SEQ, NHEAD), 32>>>(q, pos, NHEAD);
    rope_kernel<<<dim3(SEQ, NKV), 32>>>(k, pos, NKV);
    // 4. causal flash attention
    flash_kernel<<<dim3(SEQ / 64, NKV), 256>>>(attn);
    // 5. O projection + residual
    sgemm_kernel<<<dim3(DMODEL / 64, NTOK / 64), 256>>>(attn, Wo, h2, hs, NTOK, DMODEL, DMODEL);
    // 6. RMSNorm 2
    rmsnorm_kernel<<<NTOK, 256>>>(h2, ln2w, tnorm);
    // 7. router (top-2 + renormalized weights)
    router_kernel<<<NTOK, 128>>>(tnorm, Wr);
    // 8. expert assignment (counts / prefix / slots)
    assign_kernel<<<1, 256>>>();
    // 9. grouped gate+up GEMM with fused SiLU*up
    moe_gateup_kernel<<<dim3(FDIM / 64, NTOK / 64, NEXP), 256>>>(tnorm, W1, W3);
    // 10. grouped down GEMM
    moe_down_kernel<<<dim3(DMODEL / 64, NTOK / 64, NEXP), 256>>>(W2);
    // 11. combine with residual
    combine_kernel<<<NTOK, 256>>>(h2, out);
}